// round 9
// baseline (speedup 1.0000x reference)
#include <cuda_runtime.h>
#include <cuda_bf16.h>
#include <math.h>

#define B 64
#define T 512
#define E 768
#define H 72
#define BT (B*T)

#define NS   48              // k16 steps over K=768
#define NG   216             // total output cols (3*72)
#define WPIDX (NG*NS*4)      // uint4 count in packed W
#define HPAIR 36             // h-pairs per row for packed Q/K
#define TPAIR 256            // token-pairs per batch for packed V

#define QSCALE 0.11785113019775793f   // 1/sqrt(72)

// Scratch (static device globals -- no allocation in kernel_launch)
__device__ float g_V[BT*H];
__device__ unsigned g_Qp_hi[BT*HPAIR];
__device__ unsigned g_Qp_lo[BT*HPAIR];
__device__ unsigned g_Kp_hi[BT*HPAIR];
__device__ unsigned g_Kp_lo[BT*HPAIR];
// V packed transposed: [b][pair p][n]  (p = token pair 0..255, n = 0..71)
__device__ unsigned g_Vp_hi[B*TPAIR*H];
__device__ unsigned g_Vp_lo[B*TPAIR*H];
__device__ uint4 g_Wp[WPIDX];

__device__ __forceinline__ void mma16816(float* c, const unsigned* a, const unsigned* b)
{
    asm volatile(
        "mma.sync.aligned.m16n8k16.row.col.f32.bf16.bf16.f32 "
        "{%0,%1,%2,%3}, {%4,%5,%6,%7}, {%8,%9}, {%0,%1,%2,%3};\n"
        : "+f"(c[0]), "+f"(c[1]), "+f"(c[2]), "+f"(c[3])
        : "r"(a[0]), "r"(a[1]), "r"(a[2]), "r"(a[3]), "r"(b[0]), "r"(b[1]));
}

__device__ __forceinline__ unsigned pack_hi2(float a, float b)
{
    __nv_bfloat162 p = __halves2bfloat162(__float2bfloat16(a), __float2bfloat16(b));
    return *reinterpret_cast<unsigned*>(&p);
}
__device__ __forceinline__ unsigned pack_lo2(float a, float b)
{
    __nv_bfloat16 ha = __float2bfloat16(a);
    __nv_bfloat16 hb = __float2bfloat16(b);
    __nv_bfloat162 p = __halves2bfloat162(
        __float2bfloat16(a - __bfloat162float(ha)),
        __float2bfloat16(b - __bfloat162float(hb)));
    return *reinterpret_cast<unsigned*>(&p);
}
__device__ __forceinline__ void split2(float2 v, unsigned& hi, unsigned& lo)
{
    hi = pack_hi2(v.x, v.y);
    lo = pack_lo2(v.x, v.y);
}

__device__ __forceinline__ void cp16(unsigned smaddr, const void* gptr)
{
    asm volatile("cp.async.cg.shared.global [%0], [%1], 16;\n"
                 :: "r"(smaddr), "l"(gptr));
}

// ---------------------------------------------------------------------------
// prep_w: pack Wk|Wq|Wv into mma B-fragment layout (global, L2-resident)
// ---------------------------------------------------------------------------
__global__ __launch_bounds__(256) void prep_w(
    const float* __restrict__ Wk,
    const float* __restrict__ Wq,
    const float* __restrict__ Wv)
{
    int idx = blockIdx.x * 256 + threadIdx.x;
    if (idx >= WPIDX) return;
    int c2g = idx & 3;
    int s   = (idx >> 2) % NS;
    int ng  = idx / (4 * NS);
    int which = ng / H;
    int n     = ng - which * H;
    const float* __restrict__ W = (which == 0) ? Wk : ((which == 1) ? Wq : Wv);
    int k = s * 16 + c2g * 2;
    float w00 = W[(size_t)(k + 0) * H + n];
    float w01 = W[(size_t)(k + 1) * H + n];
    float w10 = W[(size_t)(k + 8) * H + n];
    float w11 = W[(size_t)(k + 9) * H + n];
    uint4 p;
    p.x = pack_hi2(w00, w01);
    p.y = pack_hi2(w10, w11);
    p.z = pack_lo2(w00, w01);
    p.w = pack_lo2(w10, w11);
    g_Wp[idx] = p;
}

// ---------------------------------------------------------------------------
// Fused projection GEMM (K,Q,V), v3:
// 384 threads / 12 warps = 4 row-groups x 3 matrix-groups.
// Warp: 32 rows (two m16 blocks) x 9 n8-tiles of ONE matrix (K, Q, or V).
// Each B-frag LDG.128 feeds 6 mmas (2x reuse). acc[9][2][4] = 72 regs.
// ---------------------------------------------------------------------------
__global__ __launch_bounds__(384) void proj_kernel(const float* __restrict__ x)
{
    const int t    = threadIdx.x;
    const int wid  = t >> 5;
    const int lane = t & 31;
    const int g    = lane >> 2;
    const int c2   = (lane & 3) * 2;
    const int c2g  = lane & 3;

    const int rowgrp = wid & 3;          // 0..3
    const int which  = wid >> 2;         // 0=K, 1=Q, 2=V
    const int ntbase = which * 9;

    const int m0 = blockIdx.x * 128 + rowgrp * 32;
    // two row-blocks: R0 rows m0+g / m0+g+8, R1 rows m0+16+g / m0+16+g+8
    const float* __restrict__ p0A = x + (size_t)(m0 + g) * E;
    const float* __restrict__ p0B = x + (size_t)(m0 + g + 8) * E;
    const float* __restrict__ p1A = x + (size_t)(m0 + 16 + g) * E;
    const float* __restrict__ p1B = x + (size_t)(m0 + 16 + g + 8) * E;

    float acc[9][2][4];
    #pragma unroll
    for (int j = 0; j < 9; j++)
        #pragma unroll
        for (int r = 0; r < 2; r++)
            #pragma unroll
            for (int i = 0; i < 4; i++) acc[j][r][i] = 0.f;

    // B-frag base pointer (stride per nt = 8*48*4 uint4)
    const uint4* __restrict__ wbase =
        g_Wp + (size_t)(g * NS) * 4 + c2g + (size_t)ntbase * (8 * NS * 4);

    float2 cur[8];
    cur[0] = *reinterpret_cast<const float2*>(p0A + c2);
    cur[1] = *reinterpret_cast<const float2*>(p0B + c2);
    cur[2] = *reinterpret_cast<const float2*>(p0A + 8 + c2);
    cur[3] = *reinterpret_cast<const float2*>(p0B + 8 + c2);
    cur[4] = *reinterpret_cast<const float2*>(p1A + c2);
    cur[5] = *reinterpret_cast<const float2*>(p1B + c2);
    cur[6] = *reinterpret_cast<const float2*>(p1A + 8 + c2);
    cur[7] = *reinterpret_cast<const float2*>(p1B + 8 + c2);

    for (int s = 0; s < NS; s++) {
        float2 nxt[8];
        if (s < NS - 1) {
            const int k = (s + 1) * 16;
            nxt[0] = *reinterpret_cast<const float2*>(p0A + k + c2);
            nxt[1] = *reinterpret_cast<const float2*>(p0B + k + c2);
            nxt[2] = *reinterpret_cast<const float2*>(p0A + k + 8 + c2);
            nxt[3] = *reinterpret_cast<const float2*>(p0B + k + 8 + c2);
            nxt[4] = *reinterpret_cast<const float2*>(p1A + k + c2);
            nxt[5] = *reinterpret_cast<const float2*>(p1B + k + c2);
            nxt[6] = *reinterpret_cast<const float2*>(p1A + k + 8 + c2);
            nxt[7] = *reinterpret_cast<const float2*>(p1B + k + 8 + c2);
        }

        unsigned ahi[2][4], alo[2][4];
        #pragma unroll
        for (int r = 0; r < 2; r++)
            #pragma unroll
            for (int i = 0; i < 4; i++)
                split2(cur[r * 4 + i], ahi[r][i], alo[r][i]);

        const uint4* __restrict__ wp = wbase + s * 4;
        #pragma unroll
        for (int j = 0; j < 9; j++) {
            uint4 bw = __ldg(wp + (size_t)j * (8 * NS * 4));
            unsigned bhi[2] = { bw.x, bw.y };
            unsigned blo[2] = { bw.z, bw.w };
            #pragma unroll
            for (int r = 0; r < 2; r++) {
                mma16816(acc[j][r], ahi[r], bhi);
                mma16816(acc[j][r], ahi[r], blo);
                mma16816(acc[j][r], alo[r], bhi);
            }
        }

        #pragma unroll
        for (int i = 0; i < 8; i++) cur[i] = nxt[i];
    }

    // Epilogue (warp-uniform `which`): K packed, Q packed prescaled, V fp32
    #pragma unroll
    for (int r = 0; r < 2; r++) {
        const size_t rA = (size_t)(m0 + r * 16 + g);
        const size_t rB = (size_t)(m0 + r * 16 + g + 8);
        if (which == 0) {
            #pragma unroll
            for (int j = 0; j < 9; j++) {
                const int pp = j * 4 + c2g;
                g_Kp_hi[rA * HPAIR + pp] = pack_hi2(acc[j][r][0], acc[j][r][1]);
                g_Kp_lo[rA * HPAIR + pp] = pack_lo2(acc[j][r][0], acc[j][r][1]);
                g_Kp_hi[rB * HPAIR + pp] = pack_hi2(acc[j][r][2], acc[j][r][3]);
                g_Kp_lo[rB * HPAIR + pp] = pack_lo2(acc[j][r][2], acc[j][r][3]);
            }
        } else if (which == 1) {
            #pragma unroll
            for (int j = 0; j < 9; j++) {
                const int pp = j * 4 + c2g;
                float q0 = acc[j][r][0] * QSCALE, q1 = acc[j][r][1] * QSCALE;
                float q2 = acc[j][r][2] * QSCALE, q3 = acc[j][r][3] * QSCALE;
                g_Qp_hi[rA * HPAIR + pp] = pack_hi2(q0, q1);
                g_Qp_lo[rA * HPAIR + pp] = pack_lo2(q0, q1);
                g_Qp_hi[rB * HPAIR + pp] = pack_hi2(q2, q3);
                g_Qp_lo[rB * HPAIR + pp] = pack_lo2(q2, q3);
            }
        } else {
            #pragma unroll
            for (int j = 0; j < 9; j++) {
                const int col = j * 8 + c2;
                *reinterpret_cast<float2*>(&g_V[rA * H + col]) =
                    make_float2(acc[j][r][0], acc[j][r][1]);
                *reinterpret_cast<float2*>(&g_V[rB * H + col]) =
                    make_float2(acc[j][r][2], acc[j][r][3]);
            }
        }
    }
}

// ---------------------------------------------------------------------------
// vpack: fp32 V -> hi/lo bf16x2 token-pairs, TRANSPOSED layout [b][p][n]
// ---------------------------------------------------------------------------
__global__ __launch_bounds__(256) void vpack_kernel()
{
    int idx = blockIdx.x * 256 + threadIdx.x;   // over B*TPAIR*H, n fastest
    if (idx >= B * TPAIR * H) return;
    int n   = idx % H;
    int rem = idx / H;
    int p   = rem % TPAIR;
    int b   = rem / TPAIR;
    float v0 = g_V[((size_t)b * T + 2 * p)     * H + n];
    float v1 = g_V[((size_t)b * T + 2 * p + 1) * H + n];
    g_Vp_hi[idx] = pack_hi2(v0, v1);
    g_Vp_lo[idx] = pack_lo2(v0, v1);
}

// ---------------------------------------------------------------------------
// Tensor-core flash attention, smem-staged with cp.async double buffering.
// (unchanged from round 6)
// ---------------------------------------------------------------------------
#define STG_U32 9216
#define KOFF_L  2304
#define VOFF_H  4608
#define VOFF_L  6912

__global__ __launch_bounds__(128) void attn_kernel(float* __restrict__ out)
{
    extern __shared__ unsigned smn[];
    const unsigned smbase = (unsigned)__cvta_generic_to_shared(smn);

    const int qt = (int)(gridDim.x - 1 - blockIdx.x);   // heavy tiles first
    const int b  = blockIdx.y;
    const int t  = threadIdx.x;
    const int w    = t >> 5;
    const int lane = t & 31;
    const int g    = lane >> 2;
    const int li   = lane & 3;

    const int row0 = qt * 64 + w * 16;
    const size_t qbase = (size_t)b * T + row0;

    unsigned qhi[5][4], qlo[5][4];
    #pragma unroll
    for (int ks = 0; ks < 5; ks++) {
        if (ks < 4) {
            const int p0 = ks * 8 + li, p1 = ks * 8 + 4 + li;
            qhi[ks][0] = g_Qp_hi[(qbase + g)     * HPAIR + p0];
            qhi[ks][1] = g_Qp_hi[(qbase + g + 8) * HPAIR + p0];
            qhi[ks][2] = g_Qp_hi[(qbase + g)     * HPAIR + p1];
            qhi[ks][3] = g_Qp_hi[(qbase + g + 8) * HPAIR + p1];
            qlo[ks][0] = g_Qp_lo[(qbase + g)     * HPAIR + p0];
            qlo[ks][1] = g_Qp_lo[(qbase + g + 8) * HPAIR + p0];
            qlo[ks][2] = g_Qp_lo[(qbase + g)     * HPAIR + p1];
            qlo[ks][3] = g_Qp_lo[(qbase + g + 8) * HPAIR + p1];
        } else {
            const int p0 = 32 + li;
            qhi[4][0] = g_Qp_hi[(qbase + g)     * HPAIR + p0];
            qhi[4][1] = g_Qp_hi[(qbase + g + 8) * HPAIR + p0];
            qhi[4][2] = 0; qhi[4][3] = 0;
            qlo[4][0] = g_Qp_lo[(qbase + g)     * HPAIR + p0];
            qlo[4][1] = g_Qp_lo[(qbase + g + 8) * HPAIR + p0];
            qlo[4][2] = 0; qlo[4][3] = 0;
        }
    }

    auto fill = [&](int stage, int kt) {
        const unsigned dst = smbase + stage * (STG_U32 * 4);
        const char* sK_h = (const char*)(g_Kp_hi + ((size_t)b * T + kt * 64) * HPAIR);
        const char* sK_l = (const char*)(g_Kp_lo + ((size_t)b * T + kt * 64) * HPAIR);
        const char* sV_h = (const char*)(g_Vp_hi + ((size_t)b * TPAIR + kt * 32) * H);
        const char* sV_l = (const char*)(g_Vp_lo + ((size_t)b * TPAIR + kt * 32) * H);
        for (int i = t; i < 576; i += 128) {
            const int o = i * 16;
            cp16(dst + o,                 sK_h + o);
            cp16(dst + KOFF_L * 4 + o,    sK_l + o);
            cp16(dst + VOFF_H * 4 + o,    sV_h + o);
            cp16(dst + VOFF_L * 4 + o,    sV_l + o);
        }
    };

    fill(0, 0);
    asm volatile("cp.async.commit_group;\n");

    float m0r = -1e30f, m1r = -1e30f, l0 = 0.f, l1 = 0.f;
    float o[9][4];
    #pragma unroll
    for (int j = 0; j < 9; j++)
        #pragma unroll
        for (int i = 0; i < 4; i++) o[j][i] = 0.f;

    for (int kt = 0; kt <= qt; kt++) {
        if (kt < qt) {
            fill((kt + 1) & 1, kt + 1);
            asm volatile("cp.async.commit_group;\n");
            asm volatile("cp.async.wait_group 1;\n");
        } else {
            asm volatile("cp.async.wait_group 0;\n");
        }
        __syncthreads();

        const unsigned* __restrict__ st = smn + (kt & 1) * STG_U32;
        const unsigned* __restrict__ Kh = st;
        const unsigned* __restrict__ Kl = st + KOFF_L;
        const unsigned* __restrict__ Vh = st + VOFF_H;
        const unsigned* __restrict__ Vl = st + VOFF_L;

        float s[8][4];
        #pragma unroll
        for (int nb = 0; nb < 8; nb++)
            #pragma unroll
            for (int i = 0; i < 4; i++) s[nb][i] = 0.f;

        #pragma unroll
        for (int ks = 0; ks < 5; ks++) {
            #pragma unroll
            for (int nb = 0; nb < 8; nb++) {
                const int rk = (nb * 8 + g) * HPAIR;
                unsigned bh[2], bl[2];
                if (ks < 4) {
                    bh[0] = Kh[rk + ks * 8 + li];
                    bh[1] = Kh[rk + ks * 8 + 4 + li];
                    bl[0] = Kl[rk + ks * 8 + li];
                    bl[1] = Kl[rk + ks * 8 + 4 + li];
                } else {
                    bh[0] = Kh[rk + 32 + li]; bh[1] = 0;
                    bl[0] = Kl[rk + 32 + li]; bl[1] = 0;
                }
                mma16816(s[nb], qhi[ks], bh);
                mma16816(s[nb], qhi[ks], bl);
                mma16816(s[nb], qlo[ks], bh);
            }
        }

        if (kt == qt) {
            const int r0g = row0 + g, r1g = row0 + g + 8;
            #pragma unroll
            for (int nb = 0; nb < 8; nb++) {
                const int c = qt * 64 + nb * 8 + 2 * li;
                if (c     > r0g) s[nb][0] = -1e30f;
                if (c + 1 > r0g) s[nb][1] = -1e30f;
                if (c     > r1g) s[nb][2] = -1e30f;
                if (c + 1 > r1g) s[nb][3] = -1e30f;
            }
        }

        float rm0 = -1e30f, rm1 = -1e30f;
        #pragma unroll
        for (int nb = 0; nb < 8; nb++) {
            rm0 = fmaxf(rm0, fmaxf(s[nb][0], s[nb][1]));
            rm1 = fmaxf(rm1, fmaxf(s[nb][2], s[nb][3]));
        }
        rm0 = fmaxf(rm0, __shfl_xor_sync(0xffffffffu, rm0, 1));
        rm0 = fmaxf(rm0, __shfl_xor_sync(0xffffffffu, rm0, 2));
        rm1 = fmaxf(rm1, __shfl_xor_sync(0xffffffffu, rm1, 1));
        rm1 = fmaxf(rm1, __shfl_xor_sync(0xffffffffu, rm1, 2));

        const float mn0 = fmaxf(m0r, rm0);
        const float mn1 = fmaxf(m1r, rm1);
        const float sc0 = __expf(m0r - mn0);
        const float sc1 = __expf(m1r - mn1);

        float rs0 = 0.f, rs1 = 0.f;
        #pragma unroll
        for (int nb = 0; nb < 8; nb++) {
            s[nb][0] = __expf(s[nb][0] - mn0);
            s[nb][1] = __expf(s[nb][1] - mn0);
            s[nb][2] = __expf(s[nb][2] - mn1);
            s[nb][3] = __expf(s[nb][3] - mn1);
            rs0 += s[nb][0] + s[nb][1];
            rs1 += s[nb][2] + s[nb][3];
        }
        rs0 += __shfl_xor_sync(0xffffffffu, rs0, 1);
        rs0 += __shfl_xor_sync(0xffffffffu, rs0, 2);
        rs1 += __shfl_xor_sync(0xffffffffu, rs1, 1);
        rs1 += __shfl_xor_sync(0xffffffffu, rs1, 2);

        l0 = l0 * sc0 + rs0;
        l1 = l1 * sc1 + rs1;
        m0r = mn0; m1r = mn1;

        #pragma unroll
        for (int j = 0; j < 9; j++) {
            o[j][0] *= sc0; o[j][1] *= sc0;
            o[j][2] *= sc1; o[j][3] *= sc1;
        }

        #pragma unroll
        for (int ks = 0; ks < 4; ks++) {
            unsigned ph[4], pl[4];
            ph[0] = pack_hi2(s[2*ks][0],   s[2*ks][1]);
            pl[0] = pack_lo2(s[2*ks][0],   s[2*ks][1]);
            ph[1] = pack_hi2(s[2*ks][2],   s[2*ks][3]);
            pl[1] = pack_lo2(s[2*ks][2],   s[2*ks][3]);
            ph[2] = pack_hi2(s[2*ks+1][0], s[2*ks+1][1]);
            pl[2] = pack_lo2(s[2*ks+1][0], s[2*ks+1][1]);
            ph[3] = pack_hi2(s[2*ks+1][2], s[2*ks+1][3]);
            pl[3] = pack_lo2(s[2*ks+1][2], s[2*ks+1][3]);

            const int rv0 = (ks * 8 + li) * H;
            const int rv1 = (ks * 8 + 4 + li) * H;
            #pragma unroll
            for (int nb = 0; nb < 9; nb++) {
                const int cn = nb * 8 + g;
                unsigned vh[2] = { Vh[rv0 + cn], Vh[rv1 + cn] };
                unsigned vl[2] = { Vl[rv0 + cn], Vl[rv1 + cn] };
                mma16816(o[nb], ph, vh);
                mma16816(o[nb], ph, vl);
                mma16816(o[nb], pl, vh);
            }
        }
        __syncthreads();
    }

    const float inv0 = 1.f / l0;
    const float inv1 = 1.f / l1;
    float* od0 = out + (qbase + g)     * H;
    float* od1 = out + (qbase + g + 8) * H;
    #pragma unroll
    for (int nb = 0; nb < 9; nb++) {
        const int col = nb * 8 + 2 * li;
        *reinterpret_cast<float2*>(od0 + col) = make_float2(o[nb][0] * inv0, o[nb][1] * inv0);
        *reinterpret_cast<float2*>(od1 + col) = make_float2(o[nb][2] * inv1, o[nb][3] * inv1);
    }
}

// ---------------------------------------------------------------------------
extern "C" void kernel_launch(void* const* d_in, const int* in_sizes, int n_in,
                              void* d_out, int out_size)
{
    const float* x  = (const float*)d_in[0];
    const float* Wk = (const float*)d_in[1];
    const float* Wq = (const float*)d_in[2];
    const float* Wv = (const float*)d_in[3];
    float* out = (float*)d_out;

    prep_w<<<(WPIDX + 255) / 256, 256>>>(Wk, Wq, Wv);
    proj_kernel<<<BT / 128, 384>>>(x);
    vpack_kernel<<<(B * TPAIR * H + 255) / 256, 256>>>();

    cudaFuncSetAttribute(attn_kernel, cudaFuncAttributeMaxDynamicSharedMemorySize, 73728);
    attn_kernel<<<dim3(T / 64, B), 128, 73728>>>(out);
}